// round 16
// baseline (speedup 1.0000x reference)
#include <cuda_runtime.h>
#include <cuda_fp16.h>
#include <cuda_bf16.h>
#include <cstdint>

typedef unsigned long long u64;
typedef unsigned int u32;

#define SEQ   4096
#define BATCH 2
#define EMB   768
#define NHEAD 12
#define HDIM  64
#define HALFW 256
#define MROWS (SEQ * BATCH)   // 8192

// q scaled by 0.125 * log2(e) so softmax can use exp2
#define QSCALE 0.18033688011112042f

// ---------------- device scratch ----------------
__device__ __nv_bfloat16 g_qkvh[3][(size_t)BATCH * NHEAD * SEQ * HDIM];
__device__ __nv_bfloat16 g_qkvl[3][(size_t)BATCH * NHEAD * SEQ * HDIM];
__device__ __half g_xh[(size_t)MROWS * EMB];            // X fp16
__device__ __half g_wt[3][(size_t)EMB * EMB];           // W^T fp16 [n][k]

// ---------------- PTX helpers ----------------
__device__ __forceinline__ u32 smem_u32(const void* p) {
    u32 a;
    asm("{ .reg .u64 t; cvta.to.shared.u64 t, %1; cvt.u32.u64 %0, t; }" : "=r"(a) : "l"(p));
    return a;
}
__device__ __forceinline__ void cp_async16(u32 dst, const void* src) {
    asm volatile("cp.async.cg.shared.global [%0], [%1], 16;" :: "r"(dst), "l"(src) : "memory");
}
__device__ __forceinline__ void cp_commit() {
    asm volatile("cp.async.commit_group;" ::: "memory");
}
template <int N>
__device__ __forceinline__ void cp_wait() {
    asm volatile("cp.async.wait_group %0;" :: "n"(N) : "memory");
}
__device__ __forceinline__ void ldmx4(u32* r, u32 addr) {
    asm volatile("ldmatrix.sync.aligned.m8n8.x4.shared.b16 {%0,%1,%2,%3}, [%4];"
                 : "=r"(r[0]), "=r"(r[1]), "=r"(r[2]), "=r"(r[3]) : "r"(addr));
}
__device__ __forceinline__ void ldmx4t(u32* r, u32 addr) {
    asm volatile("ldmatrix.sync.aligned.m8n8.x4.trans.shared.b16 {%0,%1,%2,%3}, [%4];"
                 : "=r"(r[0]), "=r"(r[1]), "=r"(r[2]), "=r"(r[3]) : "r"(addr));
}
// bf16 mma (attention, 3-term split)
__device__ __forceinline__ void mma16816(float* c, const u32* a, u32 b0, u32 b1) {
    asm volatile(
        "mma.sync.aligned.m16n8k16.row.col.f32.bf16.bf16.f32 "
        "{%0,%1,%2,%3}, {%4,%5,%6,%7}, {%8,%9}, {%0,%1,%2,%3};"
        : "+f"(c[0]), "+f"(c[1]), "+f"(c[2]), "+f"(c[3])
        : "r"(a[0]), "r"(a[1]), "r"(a[2]), "r"(a[3]), "r"(b0), "r"(b1));
}
// fp16 mma (GEMM)
__device__ __forceinline__ void mma16816h(float* c, const u32* a, u32 b0, u32 b1) {
    asm volatile(
        "mma.sync.aligned.m16n8k16.row.col.f32.f16.f16.f32 "
        "{%0,%1,%2,%3}, {%4,%5,%6,%7}, {%8,%9}, {%0,%1,%2,%3};"
        : "+f"(c[0]), "+f"(c[1]), "+f"(c[2]), "+f"(c[3])
        : "r"(a[0]), "r"(a[1]), "r"(a[2]), "r"(a[3]), "r"(b0), "r"(b1));
}
__device__ __forceinline__ u32 pack_bf(float lo, float hi) {
    u32 r;
    asm("cvt.rn.bf16x2.f32 %0, %1, %2;" : "=r"(r) : "f"(hi), "f"(lo));
    return r;
}
__device__ __forceinline__ void split_pair(float p0, float p1, u32& h, u32& l) {
    h = pack_bf(p0, p1);
    const float h0 = __uint_as_float(h << 16);
    const float h1 = __uint_as_float(h & 0xffff0000u);
    l = pack_bf(p0 - h0, p1 - h1);
}

// ---------------------------------------------------------------------------
// merged prep: blocks [0, XBLKS) convert X; blocks [XBLKS, XBLKS+1728) do W^T
// ---------------------------------------------------------------------------
#define XBLKS ((MROWS * EMB + 255) / 256)    // 24576

__global__ __launch_bounds__(256) void conv_xw_kernel(
    const float* __restrict__ X,
    const float* __restrict__ Wq, const float* __restrict__ Wk,
    const float* __restrict__ Wv)
{
    const int blk = blockIdx.x;
    if (blk < XBLKS) {
        const size_t i = (size_t)blk * 256 + threadIdx.x;
        if (i < (size_t)MROWS * EMB) g_xh[i] = __float2half_rn(X[i]);
        return;
    }
    // W part: 1728 blocks = (24 x 24 x 3)
    __shared__ float t[32][33];
    const int wb = blk - XBLKS;
    const int z  = wb / 576;
    const int r576 = wb % 576;
    const int bx = r576 / 24;           // n-block
    const int by = r576 % 24;           // k-block
    const float* W = (z == 0) ? Wq : (z == 1) ? Wk : Wv;
    const int n0 = bx * 32;
    const int k0 = by * 32;
    const int tx = threadIdx.x & 31;
    const int ty = threadIdx.x >> 5;
#pragma unroll
    for (int i = 0; i < 4; i++) {
        const int kk = ty + i * 8;
        t[kk][tx] = W[(size_t)(k0 + kk) * EMB + n0 + tx];
    }
    __syncthreads();
#pragma unroll
    for (int i = 0; i < 4; i++) {
        const int nn = ty + i * 8;
        g_wt[z][(size_t)(n0 + nn) * EMB + k0 + tx] = __float2half_rn(t[tx][nn]);
    }
}

// ---------------------------------------------------------------------------
// fp16 single-term QKV GEMM. CTA 128x64, 8 warps (4Mx2N), warp tile 32x32.
// BK=64, 12 chunks, 4-stage cp.async ring (prefetch depth 3). 2 CTAs/SM.
// ---------------------------------------------------------------------------
#define BK        64
#define ROWB      144
#define ATILE_B   (128 * ROWB)               // 18432
#define BTILE_B   (64 * ROWB)                // 9216
#define STAGE_B   (ATILE_B + BTILE_B)        // 27648
#define NSTAGE    4
#define GEMM_SMEM (NSTAGE * STAGE_B)         // 110592
#define NCHUNK    (EMB / BK)                 // 12
#define OFF_A     0
#define OFF_B     ATILE_B

__global__ __launch_bounds__(256, 2)
void gemm_fp16_kernel(const float* __restrict__ bq, const float* __restrict__ bk_,
                      const float* __restrict__ bv)
{
    extern __shared__ __align__(1024) char smem[];
    __shared__ float bias_sh[64];

    const int tid = threadIdx.x;
    const int wid = tid >> 5;
    const int lid = tid & 31;
    const int wm = wid >> 1;
    const int wn = wid & 1;
    const int which = blockIdx.z;
    const int m0 = blockIdx.x * 128;
    const int n0 = blockIdx.y * 64;

    const u32 sb = smem_u32(smem);

    const float* bias = (which == 0) ? bq : (which == 1) ? bk_ : bv;
    if (tid < 64) bias_sh[tid] = bias[n0 + tid];

    const __half* srcA = g_xh + (size_t)m0 * EMB;
    const __half* srcB = g_wt[which] + (size_t)n0 * EMB;

    u32 aoff[2];
#pragma unroll
    for (int mi = 0; mi < 2; mi++)
        aoff[mi] = (u32)((wm * 32 + mi * 16 + (lid & 15)) * ROWB + (lid >> 4) * 16);
    u32 boff[2];
#pragma unroll
    for (int j = 0; j < 2; j++)
        boff[j] = (u32)((wn * 32 + j * 16 + ((lid >> 4) & 1) * 8 + (lid & 7)) * ROWB
                        + ((lid >> 3) & 1) * 16);

    float acc[2][4][4];
#pragma unroll
    for (int mi = 0; mi < 2; mi++)
#pragma unroll
        for (int ni = 0; ni < 4; ni++)
#pragma unroll
            for (int q = 0; q < 4; q++) acc[mi][ni][q] = 0.0f;

    auto load_chunk = [&](int c, int s) {
        const int k0 = c * BK;
        const u32 stage = sb + s * STAGE_B;
#pragma unroll
        for (int i = 0; i < 4; i++) {
            const int g   = tid + i * 256;
            const int row = g >> 3;
            const int prt = g & 7;
            cp_async16(stage + OFF_A + row * ROWB + prt * 16,
                       srcA + (size_t)row * EMB + k0 + prt * 8);
        }
#pragma unroll
        for (int i = 0; i < 2; i++) {
            const int g   = tid + i * 256;
            const int row = g >> 3;
            const int prt = g & 7;
            cp_async16(stage + OFF_B + row * ROWB + prt * 16,
                       srcB + (size_t)row * EMB + k0 + prt * 8);
        }
        cp_commit();
    };

    auto compute_chunk = [&](int s) {
        const u32 stage = sb + s * STAGE_B;
        const u32 aB = stage + OFF_A, bB = stage + OFF_B;
#pragma unroll
        for (int ks = 0; ks < 4; ks++) {
            const u32 kadv = ks * 32;
            u32 af[2][4], bf[2][4];
#pragma unroll
            for (int mi = 0; mi < 2; mi++) ldmx4(af[mi], aB + aoff[mi] + kadv);
#pragma unroll
            for (int j = 0; j < 2; j++)    ldmx4(bf[j], bB + boff[j] + kadv);
#pragma unroll
            for (int mi = 0; mi < 2; mi++)
#pragma unroll
                for (int ni = 0; ni < 4; ni++) {
                    const int j = ni >> 1, e = (ni & 1) * 2;
                    mma16816h(acc[mi][ni], af[mi], bf[j][e], bf[j][e + 1]);
                }
        }
    };

    // 4-stage pipeline, prefetch depth 3
    load_chunk(0, 0);
    load_chunk(1, 1);
    load_chunk(2, 2);
    for (int c = 0; c < NCHUNK; c++) {
        cp_wait<2>();           // chunk c landed (c+1, c+2 may be in flight)
        __syncthreads();
        if (c + 3 < NCHUNK) load_chunk(c + 3, (c + 3) % NSTAGE);
        compute_chunk(c % NSTAGE);
    }
    __syncthreads();

    const float scale = (which == 0) ? QSCALE : 1.0f;
    const int row_in_q = lid >> 2;
    const int col_pair = (lid & 3) * 2;
    const int h = n0 >> 6;
#pragma unroll
    for (int mi = 0; mi < 2; mi++) {
#pragma unroll
        for (int ni = 0; ni < 4; ni++) {
            const int ncol = wn * 32 + ni * 8 + col_pair;
            const int d = (n0 + ncol) & 63;
            const float b0v = bias_sh[ncol], b1v = bias_sh[ncol + 1];
#pragma unroll
            for (int half = 0; half < 2; half++) {
                const int m = m0 + wm * 32 + mi * 16 + row_in_q + half * 8;
                const int s_ = m >> 1;
                const int b_ = m & 1;
                const float v0 = (acc[mi][ni][half * 2 + 0] + b0v) * scale;
                const float v1 = (acc[mi][ni][half * 2 + 1] + b1v) * scale;
                u32 hpk, lpk;
                split_pair(v0, v1, hpk, lpk);
                const size_t idx = ((size_t)(b_ * NHEAD + h) * SEQ + s_) * HDIM + d;
                *(u32*)(g_qkvh[which] + idx) = hpk;
                *(u32*)(g_qkvl[which] + idx) = lpk;
            }
        }
    }
}

// ---------------------------------------------------------------------------
// Banded local attention — R13/R15 exact (proven: 121.9us, rel_err 3.25e-4).
// ---------------------------------------------------------------------------
#define AROWB   144
#define ATILE   (64 * AROWB)
#define AQ_B    (2 * ATILE)
#define ASTAGE  (4 * ATILE)
#define AT_SMEM (AQ_B + 2 * ASTAGE)          // 92160

__global__ __launch_bounds__(128, 2)
void attn_mma_kernel(float* __restrict__ out)
{
    extern __shared__ __align__(1024) char smem[];
    const int tid = threadIdx.x;
    const int wid = tid >> 5;
    const int lid = tid & 31;
    const int q0 = blockIdx.x * 64;
    const int h  = blockIdx.y;
    const int b  = blockIdx.z;
    const size_t bh = (size_t)(b * NHEAD + h) * SEQ * HDIM;

    const u32 sb = smem_u32(smem);

    int kt0 = q0 - HALFW; if (kt0 < 0) kt0 = 0;
    int kt1 = q0 + HALFW; if (kt1 > SEQ - 64) kt1 = SEQ - 64;
    const int T = (kt1 - kt0) / 64 + 1;

    auto load_q = [&] {
#pragma unroll
        for (int tq = 0; tq < 2; tq++) {
            const __nv_bfloat16* src =
                ((tq == 0) ? g_qkvh[0] : g_qkvl[0]) + bh + (size_t)q0 * HDIM;
            const u32 dstb = sb + tq * ATILE;
#pragma unroll
            for (int i = 0; i < 4; i++) {
                const int g = tid + i * 128;
                const int row = g >> 3, c = g & 7;
                cp_async16(dstb + row * AROWB + c * 16, src + row * HDIM + c * 8);
            }
        }
    };
    auto load_kv = [&](int t, int s) {
        const int kt = kt0 + t * 64;
        const u32 stb = sb + AQ_B + s * ASTAGE;
        const __nv_bfloat16* srcs[4] = {
            g_qkvh[1] + bh + (size_t)kt * HDIM, g_qkvl[1] + bh + (size_t)kt * HDIM,
            g_qkvh[2] + bh + (size_t)kt * HDIM, g_qkvl[2] + bh + (size_t)kt * HDIM };
#pragma unroll
        for (int tt = 0; tt < 4; tt++) {
            const u32 dstb = stb + tt * ATILE;
#pragma unroll
            for (int i = 0; i < 4; i++) {
                const int g = tid + i * 128;
                const int row = g >> 3, c = g & 7;
                cp_async16(dstb + row * AROWB + c * 16, srcs[tt] + row * HDIM + c * 8);
            }
        }
    };

    load_q();
    load_kv(0, 0);
    cp_commit();

    const u32 a_off = (u32)((wid * 16 + (lid & 7) + ((lid >> 3) & 1) * 8) * AROWB
                            + (lid >> 4) * 16);
    u32 kb_off[4];
#pragma unroll
    for (int p = 0; p < 4; p++)
        kb_off[p] = (u32)((16 * p + ((lid >> 4) & 1) * 8 + (lid & 7)) * AROWB
                          + ((lid >> 3) & 1) * 16);
    const u32 v_off = (u32)((lid & 15) * AROWB + (lid >> 4) * 16);

    u32 qf[2][4][4];
    float o[8][4];
    float m_r[2] = { -1e30f, -1e30f };
    float l_r[2] = { 0.0f, 0.0f };
#pragma unroll
    for (int ni = 0; ni < 8; ni++)
#pragma unroll
        for (int e = 0; e < 4; e++) o[ni][e] = 0.0f;

    const int r_lane = lid >> 2;
    const int c_lane = (lid & 3) * 2;

    for (int t = 0; t < T; t++) {
        if (t + 1 < T) {
            load_kv(t + 1, (t + 1) & 1);
            cp_commit();
            cp_wait<1>();
        } else {
            cp_wait<0>();
        }
        __syncthreads();

        if (t == 0) {
#pragma unroll
            for (int ks = 0; ks < 4; ks++) {
                ldmx4(qf[0][ks], sb + 0 * ATILE + a_off + ks * 32);
                ldmx4(qf[1][ks], sb + 1 * ATILE + a_off + ks * 32);
            }
        }

        const int kt = kt0 + t * 64;
        const u32 st = sb + AQ_B + (t & 1) * ASTAGE;
        const u32 kHi = st + 0 * ATILE, kLo = st + 1 * ATILE;
        const u32 vHi = st + 2 * ATILE, vLo = st + 3 * ATILE;

        float sc[8][4];
#pragma unroll
        for (int ni = 0; ni < 8; ni++)
#pragma unroll
            for (int e = 0; e < 4; e++) sc[ni][e] = 0.0f;

#pragma unroll
        for (int ks = 0; ks < 4; ks++) {
            u32 bh4[4][4], bl4[4][4];
#pragma unroll
            for (int p = 0; p < 4; p++) {
                ldmx4(bh4[p], kHi + kb_off[p] + ks * 32);
                ldmx4(bl4[p], kLo + kb_off[p] + ks * 32);
            }
#pragma unroll
            for (int p = 0; p < 4; p++) {
                mma16816(sc[2 * p + 0], qf[0][ks], bh4[p][0], bh4[p][1]);
                mma16816(sc[2 * p + 1], qf[0][ks], bh4[p][2], bh4[p][3]);
            }
#pragma unroll
            for (int p = 0; p < 4; p++) {
                mma16816(sc[2 * p + 0], qf[0][ks], bl4[p][0], bl4[p][1]);
                mma16816(sc[2 * p + 1], qf[0][ks], bl4[p][2], bl4[p][3]);
            }
#pragma unroll
            for (int p = 0; p < 4; p++) {
                mma16816(sc[2 * p + 0], qf[1][ks], bh4[p][0], bh4[p][1]);
                mma16816(sc[2 * p + 1], qf[1][ks], bh4[p][2], bh4[p][3]);
            }
        }

        if (kt == q0 - HALFW || kt == q0 + HALFW) {
#pragma unroll
            for (int ni = 0; ni < 8; ni++)
#pragma unroll
                for (int e = 0; e < 4; e++) {
                    const int kc = kt + ni * 8 + c_lane + (e & 1);
                    const int qa = q0 + wid * 16 + r_lane + ((e >> 1) << 3);
                    const int d = kc - qa;
                    if (d < -HALFW || d > HALFW) sc[ni][e] = -3.0e38f;
                }
        }

        float mx0 = -3.0e38f, mx1 = -3.0e38f;
#pragma unroll
        for (int ni = 0; ni < 8; ni++) {
            mx0 = fmaxf(mx0, fmaxf(sc[ni][0], sc[ni][1]));
            mx1 = fmaxf(mx1, fmaxf(sc[ni][2], sc[ni][3]));
        }
        mx0 = fmaxf(mx0, __shfl_xor_sync(0xffffffffu, mx0, 1));
        mx0 = fmaxf(mx0, __shfl_xor_sync(0xffffffffu, mx0, 2));
        mx1 = fmaxf(mx1, __shfl_xor_sync(0xffffffffu, mx1, 1));
        mx1 = fmaxf(mx1, __shfl_xor_sync(0xffffffffu, mx1, 2));

        const float nm0 = fmaxf(m_r[0], mx0);
        const float nm1 = fmaxf(m_r[1], mx1);
        const float c0 = exp2f(m_r[0] - nm0);
        const float c1 = exp2f(m_r[1] - nm1);
        float s0 = 0.0f, s1 = 0.0f;
#pragma unroll
        for (int ni = 0; ni < 8; ni++) {
            sc[ni][0] = exp2f(sc[ni][0] - nm0); s0 += sc[ni][0];
            sc[ni][1] = exp2f(sc[ni][1] - nm0); s0 += sc[ni][1];
            sc[ni][2] = exp2f(sc[ni][2] - nm1); s1 += sc[ni][2];
            sc[ni][3] = exp2f(sc[ni][3] - nm1); s1 += sc[ni][3];
        }
        s0 += __shfl_xor_sync(0xffffffffu, s0, 1);
        s0 += __shfl_xor_sync(0xffffffffu, s0, 2);
        s1 += __shfl_xor_sync(0xffffffffu, s1, 1);
        s1 += __shfl_xor_sync(0xffffffffu, s1, 2);
        l_r[0] = l_r[0] * c0 + s0; m_r[0] = nm0;
        l_r[1] = l_r[1] * c1 + s1; m_r[1] = nm1;
#pragma unroll
        for (int ni = 0; ni < 8; ni++) {
            o[ni][0] *= c0; o[ni][1] *= c0;
            o[ni][2] *= c1; o[ni][3] *= c1;
        }

#pragma unroll
        for (int ks = 0; ks < 4; ks++) {
            u32 ph[4], pl[4];
            split_pair(sc[2 * ks + 0][0], sc[2 * ks + 0][1], ph[0], pl[0]);
            split_pair(sc[2 * ks + 0][2], sc[2 * ks + 0][3], ph[1], pl[1]);
            split_pair(sc[2 * ks + 1][0], sc[2 * ks + 1][1], ph[2], pl[2]);
            split_pair(sc[2 * ks + 1][2], sc[2 * ks + 1][3], ph[3], pl[3]);
            u32 vh4[4][4], vl4[4][4];
#pragma unroll
            for (int p = 0; p < 4; p++) {
                ldmx4t(vh4[p], vHi + v_off + ks * 16 * AROWB + p * 32);
                ldmx4t(vl4[p], vLo + v_off + ks * 16 * AROWB + p * 32);
            }
#pragma unroll
            for (int p = 0; p < 4; p++) {
                mma16816(o[2 * p + 0], ph, vh4[p][0], vh4[p][1]);
                mma16816(o[2 * p + 1], ph, vh4[p][2], vh4[p][3]);
            }
#pragma unroll
            for (int p = 0; p < 4; p++) {
                mma16816(o[2 * p + 0], ph, vl4[p][0], vl4[p][1]);
                mma16816(o[2 * p + 1], ph, vl4[p][2], vl4[p][3]);
            }
#pragma unroll
            for (int p = 0; p < 4; p++) {
                mma16816(o[2 * p + 0], pl, vh4[p][0], vh4[p][1]);
                mma16816(o[2 * p + 1], pl, vh4[p][2], vh4[p][3]);
            }
        }
        __syncthreads();
    }

    const float inv0 = 1.0f / l_r[0];
    const float inv1 = 1.0f / l_r[1];
    const int s_row0 = q0 + wid * 16 + r_lane;
#pragma unroll
    for (int ni = 0; ni < 8; ni++) {
        const int dcol = ni * 8 + c_lane;
        const size_t base = (size_t)b * EMB + h * HDIM + dcol;
        float2 r0, r1;
        r0.x = o[ni][0] * inv0; r0.y = o[ni][1] * inv0;
        r1.x = o[ni][2] * inv1; r1.y = o[ni][3] * inv1;
        *(float2*)(out + (size_t)s_row0 * (BATCH * EMB) + base) = r0;
        *(float2*)(out + (size_t)(s_row0 + 8) * (BATCH * EMB) + base) = r1;
    }
}

extern "C" void kernel_launch(void* const* d_in, const int* in_sizes, int n_in,
                              void* d_out, int out_size) {
    (void)in_sizes; (void)n_in; (void)out_size;
    const float* X  = (const float*)d_in[0];
    const float* Wq = (const float*)d_in[1];
    const float* bq = (const float*)d_in[2];
    const float* Wk = (const float*)d_in[3];
    const float* bk = (const float*)d_in[4];
    const float* Wv = (const float*)d_in[5];
    const float* bv = (const float*)d_in[6];
    float* out = (float*)d_out;

    static int attr_set = 0;
    if (!attr_set) {
        cudaFuncSetAttribute(gemm_fp16_kernel,
                             cudaFuncAttributeMaxDynamicSharedMemorySize, GEMM_SMEM);
        cudaFuncSetAttribute(attn_mma_kernel,
                             cudaFuncAttributeMaxDynamicSharedMemorySize, AT_SMEM);
        attr_set = 1;
    }

    conv_xw_kernel<<<XBLKS + 1728, 256>>>(X, Wq, Wk, Wv);

    dim3 gg(MROWS / 128, EMB / 64, 3);    // (64, 12, 3)
    gemm_fp16_kernel<<<gg, 256, GEMM_SMEM>>>(bq, bk, bv);

    dim3 ga(SEQ / 64, NHEAD, BATCH);
    attn_mma_kernel<<<ga, 128, AT_SMEM>>>(out);
}

// round 17
// speedup vs baseline: 1.0573x; 1.0573x over previous
#include <cuda_runtime.h>
#include <cuda_fp16.h>
#include <cuda_bf16.h>
#include <cstdint>

typedef unsigned long long u64;
typedef unsigned int u32;

#define SEQ   4096
#define BATCH 2
#define EMB   768
#define NHEAD 12
#define HDIM  64
#define HALFW 256
#define MROWS (SEQ * BATCH)   // 8192

// q scaled by 0.125 * log2(e) so softmax can use exp2
#define QSCALE 0.18033688011112042f

// ---------------- device scratch ----------------
__device__ __nv_bfloat16 g_qkvh[3][(size_t)BATCH * NHEAD * SEQ * HDIM];
__device__ __nv_bfloat16 g_qkvl[3][(size_t)BATCH * NHEAD * SEQ * HDIM];
__device__ __half g_xh[(size_t)MROWS * EMB];            // X fp16
__device__ __half g_wt[3][(size_t)EMB * EMB];           // W^T fp16 [n][k]

// ---------------- PTX helpers ----------------
__device__ __forceinline__ u32 smem_u32(const void* p) {
    u32 a;
    asm("{ .reg .u64 t; cvta.to.shared.u64 t, %1; cvt.u32.u64 %0, t; }" : "=r"(a) : "l"(p));
    return a;
}
__device__ __forceinline__ void cp_async16(u32 dst, const void* src) {
    asm volatile("cp.async.cg.shared.global [%0], [%1], 16;" :: "r"(dst), "l"(src) : "memory");
}
__device__ __forceinline__ void cp_commit() {
    asm volatile("cp.async.commit_group;" ::: "memory");
}
template <int N>
__device__ __forceinline__ void cp_wait() {
    asm volatile("cp.async.wait_group %0;" :: "n"(N) : "memory");
}
__device__ __forceinline__ void ldmx4(u32* r, u32 addr) {
    asm volatile("ldmatrix.sync.aligned.m8n8.x4.shared.b16 {%0,%1,%2,%3}, [%4];"
                 : "=r"(r[0]), "=r"(r[1]), "=r"(r[2]), "=r"(r[3]) : "r"(addr));
}
__device__ __forceinline__ void ldmx4t(u32* r, u32 addr) {
    asm volatile("ldmatrix.sync.aligned.m8n8.x4.trans.shared.b16 {%0,%1,%2,%3}, [%4];"
                 : "=r"(r[0]), "=r"(r[1]), "=r"(r[2]), "=r"(r[3]) : "r"(addr));
}
// bf16 mma (attention, 3-term split)
__device__ __forceinline__ void mma16816(float* c, const u32* a, u32 b0, u32 b1) {
    asm volatile(
        "mma.sync.aligned.m16n8k16.row.col.f32.bf16.bf16.f32 "
        "{%0,%1,%2,%3}, {%4,%5,%6,%7}, {%8,%9}, {%0,%1,%2,%3};"
        : "+f"(c[0]), "+f"(c[1]), "+f"(c[2]), "+f"(c[3])
        : "r"(a[0]), "r"(a[1]), "r"(a[2]), "r"(a[3]), "r"(b0), "r"(b1));
}
// fp16 mma (GEMM)
__device__ __forceinline__ void mma16816h(float* c, const u32* a, u32 b0, u32 b1) {
    asm volatile(
        "mma.sync.aligned.m16n8k16.row.col.f32.f16.f16.f32 "
        "{%0,%1,%2,%3}, {%4,%5,%6,%7}, {%8,%9}, {%0,%1,%2,%3};"
        : "+f"(c[0]), "+f"(c[1]), "+f"(c[2]), "+f"(c[3])
        : "r"(a[0]), "r"(a[1]), "r"(a[2]), "r"(a[3]), "r"(b0), "r"(b1));
}
__device__ __forceinline__ u32 pack_bf(float lo, float hi) {
    u32 r;
    asm("cvt.rn.bf16x2.f32 %0, %1, %2;" : "=r"(r) : "f"(hi), "f"(lo));
    return r;
}
__device__ __forceinline__ void split_pair(float p0, float p1, u32& h, u32& l) {
    h = pack_bf(p0, p1);
    const float h0 = __uint_as_float(h << 16);
    const float h1 = __uint_as_float(h & 0xffff0000u);
    l = pack_bf(p0 - h0, p1 - h1);
}

// ---------------------------------------------------------------------------
// merged prep: blocks [0, XBLKS) convert X; blocks [XBLKS, XBLKS+1728) do W^T
// ---------------------------------------------------------------------------
#define XBLKS ((MROWS * EMB + 255) / 256)    // 24576

__global__ __launch_bounds__(256) void conv_xw_kernel(
    const float* __restrict__ X,
    const float* __restrict__ Wq, const float* __restrict__ Wk,
    const float* __restrict__ Wv)
{
    const int blk = blockIdx.x;
    if (blk < XBLKS) {
        const size_t i = (size_t)blk * 256 + threadIdx.x;
        if (i < (size_t)MROWS * EMB) g_xh[i] = __float2half_rn(X[i]);
        return;
    }
    __shared__ float t[32][33];
    const int wb = blk - XBLKS;
    const int z  = wb / 576;
    const int r576 = wb % 576;
    const int bx = r576 / 24;
    const int by = r576 % 24;
    const float* W = (z == 0) ? Wq : (z == 1) ? Wk : Wv;
    const int n0 = bx * 32;
    const int k0 = by * 32;
    const int tx = threadIdx.x & 31;
    const int ty = threadIdx.x >> 5;
#pragma unroll
    for (int i = 0; i < 4; i++) {
        const int kk = ty + i * 8;
        t[kk][tx] = W[(size_t)(k0 + kk) * EMB + n0 + tx];
    }
    __syncthreads();
#pragma unroll
    for (int i = 0; i < 4; i++) {
        const int nn = ty + i * 8;
        g_wt[z][(size_t)(n0 + nn) * EMB + k0 + tx] = __float2half_rn(t[tx][nn]);
    }
}

// ---------------------------------------------------------------------------
// fp16 single-term QKV GEMM — R15-proven config. CTA 128x64, 8 warps (4Mx2N),
// warp tile 32x32, BK=64, 12 chunks, 3-stage cp.async ring, 2 CTAs/SM.
// ---------------------------------------------------------------------------
#define BK        64
#define ROWB      144
#define ATILE_B   (128 * ROWB)               // 18432
#define BTILE_B   (64 * ROWB)                // 9216
#define STAGE_B   (ATILE_B + BTILE_B)        // 27648
#define NSTAGE    3
#define GEMM_SMEM (NSTAGE * STAGE_B)         // 82944
#define NCHUNK    (EMB / BK)                 // 12
#define OFF_A     0
#define OFF_B     ATILE_B

__global__ __launch_bounds__(256, 2)
void gemm_fp16_kernel(const float* __restrict__ bq, const float* __restrict__ bk_,
                      const float* __restrict__ bv)
{
    extern __shared__ __align__(1024) char smem[];
    __shared__ float bias_sh[64];

    const int tid = threadIdx.x;
    const int wid = tid >> 5;
    const int lid = tid & 31;
    const int wm = wid >> 1;
    const int wn = wid & 1;
    const int which = blockIdx.z;
    const int m0 = blockIdx.x * 128;
    const int n0 = blockIdx.y * 64;

    const u32 sb = smem_u32(smem);

    const float* bias = (which == 0) ? bq : (which == 1) ? bk_ : bv;
    if (tid < 64) bias_sh[tid] = bias[n0 + tid];

    const __half* srcA = g_xh + (size_t)m0 * EMB;
    const __half* srcB = g_wt[which] + (size_t)n0 * EMB;

    u32 aoff[2];
#pragma unroll
    for (int mi = 0; mi < 2; mi++)
        aoff[mi] = (u32)((wm * 32 + mi * 16 + (lid & 15)) * ROWB + (lid >> 4) * 16);
    u32 boff[2];
#pragma unroll
    for (int j = 0; j < 2; j++)
        boff[j] = (u32)((wn * 32 + j * 16 + ((lid >> 4) & 1) * 8 + (lid & 7)) * ROWB
                        + ((lid >> 3) & 1) * 16);

    float acc[2][4][4];
#pragma unroll
    for (int mi = 0; mi < 2; mi++)
#pragma unroll
        for (int ni = 0; ni < 4; ni++)
#pragma unroll
            for (int q = 0; q < 4; q++) acc[mi][ni][q] = 0.0f;

    auto load_chunk = [&](int c, int s) {
        const int k0 = c * BK;
        const u32 stage = sb + s * STAGE_B;
#pragma unroll
        for (int i = 0; i < 4; i++) {
            const int g   = tid + i * 256;
            const int row = g >> 3;
            const int prt = g & 7;
            cp_async16(stage + OFF_A + row * ROWB + prt * 16,
                       srcA + (size_t)row * EMB + k0 + prt * 8);
        }
#pragma unroll
        for (int i = 0; i < 2; i++) {
            const int g   = tid + i * 256;
            const int row = g >> 3;
            const int prt = g & 7;
            cp_async16(stage + OFF_B + row * ROWB + prt * 16,
                       srcB + (size_t)row * EMB + k0 + prt * 8);
        }
        cp_commit();
    };

    auto compute_chunk = [&](int s) {
        const u32 stage = sb + s * STAGE_B;
        const u32 aB = stage + OFF_A, bB = stage + OFF_B;
#pragma unroll
        for (int ks = 0; ks < 4; ks++) {
            const u32 kadv = ks * 32;
            u32 af[2][4], bf[2][4];
#pragma unroll
            for (int mi = 0; mi < 2; mi++) ldmx4(af[mi], aB + aoff[mi] + kadv);
#pragma unroll
            for (int j = 0; j < 2; j++)    ldmx4(bf[j], bB + boff[j] + kadv);
#pragma unroll
            for (int mi = 0; mi < 2; mi++)
#pragma unroll
                for (int ni = 0; ni < 4; ni++) {
                    const int j = ni >> 1, e = (ni & 1) * 2;
                    mma16816h(acc[mi][ni], af[mi], bf[j][e], bf[j][e + 1]);
                }
        }
    };

    load_chunk(0, 0);
    load_chunk(1, 1);
    for (int c = 0; c < NCHUNK; c++) {
        cp_wait<1>();
        __syncthreads();
        if (c + 2 < NCHUNK) load_chunk(c + 2, (c + 2) % NSTAGE);
        compute_chunk(c % NSTAGE);
    }
    __syncthreads();

    const float scale = (which == 0) ? QSCALE : 1.0f;
    const int row_in_q = lid >> 2;
    const int col_pair = (lid & 3) * 2;
    const int h = n0 >> 6;
#pragma unroll
    for (int mi = 0; mi < 2; mi++) {
#pragma unroll
        for (int ni = 0; ni < 4; ni++) {
            const int ncol = wn * 32 + ni * 8 + col_pair;
            const int d = (n0 + ncol) & 63;
            const float b0v = bias_sh[ncol], b1v = bias_sh[ncol + 1];
#pragma unroll
            for (int half = 0; half < 2; half++) {
                const int m = m0 + wm * 32 + mi * 16 + row_in_q + half * 8;
                const int s_ = m >> 1;
                const int b_ = m & 1;
                const float v0 = (acc[mi][ni][half * 2 + 0] + b0v) * scale;
                const float v1 = (acc[mi][ni][half * 2 + 1] + b1v) * scale;
                u32 hpk, lpk;
                split_pair(v0, v1, hpk, lpk);
                const size_t idx = ((size_t)(b_ * NHEAD + h) * SEQ + s_) * HDIM + d;
                *(u32*)(g_qkvh[which] + idx) = hpk;
                *(u32*)(g_qkvl[which] + idx) = lpk;
            }
        }
    }
}

// ---------------------------------------------------------------------------
// Banded local attention — R13/R15 exact (proven: 121.9us, rel_err 3.25e-4).
// ---------------------------------------------------------------------------
#define AROWB   144
#define ATILE   (64 * AROWB)
#define AQ_B    (2 * ATILE)
#define ASTAGE  (4 * ATILE)
#define AT_SMEM (AQ_B + 2 * ASTAGE)          // 92160

__global__ __launch_bounds__(128, 2)
void attn_mma_kernel(float* __restrict__ out)
{
    extern __shared__ __align__(1024) char smem[];
    const int tid = threadIdx.x;
    const int wid = tid >> 5;
    const int lid = tid & 31;
    const int q0 = blockIdx.x * 64;
    const int h  = blockIdx.y;
    const int b  = blockIdx.z;
    const size_t bh = (size_t)(b * NHEAD + h) * SEQ * HDIM;

    const u32 sb = smem_u32(smem);

    int kt0 = q0 - HALFW; if (kt0 < 0) kt0 = 0;
    int kt1 = q0 + HALFW; if (kt1 > SEQ - 64) kt1 = SEQ - 64;
    const int T = (kt1 - kt0) / 64 + 1;

    auto load_q = [&] {
#pragma unroll
        for (int tq = 0; tq < 2; tq++) {
            const __nv_bfloat16* src =
                ((tq == 0) ? g_qkvh[0] : g_qkvl[0]) + bh + (size_t)q0 * HDIM;
            const u32 dstb = sb + tq * ATILE;
#pragma unroll
            for (int i = 0; i < 4; i++) {
                const int g = tid + i * 128;
                const int row = g >> 3, c = g & 7;
                cp_async16(dstb + row * AROWB + c * 16, src + row * HDIM + c * 8);
            }
        }
    };
    auto load_kv = [&](int t, int s) {
        const int kt = kt0 + t * 64;
        const u32 stb = sb + AQ_B + s * ASTAGE;
        const __nv_bfloat16* srcs[4] = {
            g_qkvh[1] + bh + (size_t)kt * HDIM, g_qkvl[1] + bh + (size_t)kt * HDIM,
            g_qkvh[2] + bh + (size_t)kt * HDIM, g_qkvl[2] + bh + (size_t)kt * HDIM };
#pragma unroll
        for (int tt = 0; tt < 4; tt++) {
            const u32 dstb = stb + tt * ATILE;
#pragma unroll
            for (int i = 0; i < 4; i++) {
                const int g = tid + i * 128;
                const int row = g >> 3, c = g & 7;
                cp_async16(dstb + row * AROWB + c * 16, srcs[tt] + row * HDIM + c * 8);
            }
        }
    };

    load_q();
    load_kv(0, 0);
    cp_commit();

    const u32 a_off = (u32)((wid * 16 + (lid & 7) + ((lid >> 3) & 1) * 8) * AROWB
                            + (lid >> 4) * 16);
    u32 kb_off[4];
#pragma unroll
    for (int p = 0; p < 4; p++)
        kb_off[p] = (u32)((16 * p + ((lid >> 4) & 1) * 8 + (lid & 7)) * AROWB
                          + ((lid >> 3) & 1) * 16);
    const u32 v_off = (u32)((lid & 15) * AROWB + (lid >> 4) * 16);

    u32 qf[2][4][4];
    float o[8][4];
    float m_r[2] = { -1e30f, -1e30f };
    float l_r[2] = { 0.0f, 0.0f };
#pragma unroll
    for (int ni = 0; ni < 8; ni++)
#pragma unroll
        for (int e = 0; e < 4; e++) o[ni][e] = 0.0f;

    const int r_lane = lid >> 2;
    const int c_lane = (lid & 3) * 2;

    for (int t = 0; t < T; t++) {
        if (t + 1 < T) {
            load_kv(t + 1, (t + 1) & 1);
            cp_commit();
            cp_wait<1>();
        } else {
            cp_wait<0>();
        }
        __syncthreads();

        if (t == 0) {
#pragma unroll
            for (int ks = 0; ks < 4; ks++) {
                ldmx4(qf[0][ks], sb + 0 * ATILE + a_off + ks * 32);
                ldmx4(qf[1][ks], sb + 1 * ATILE + a_off + ks * 32);
            }
        }

        const int kt = kt0 + t * 64;
        const u32 st = sb + AQ_B + (t & 1) * ASTAGE;
        const u32 kHi = st + 0 * ATILE, kLo = st + 1 * ATILE;
        const u32 vHi = st + 2 * ATILE, vLo = st + 3 * ATILE;

        float sc[8][4];
#pragma unroll
        for (int ni = 0; ni < 8; ni++)
#pragma unroll
            for (int e = 0; e < 4; e++) sc[ni][e] = 0.0f;

#pragma unroll
        for (int ks = 0; ks < 4; ks++) {
            u32 bh4[4][4], bl4[4][4];
#pragma unroll
            for (int p = 0; p < 4; p++) {
                ldmx4(bh4[p], kHi + kb_off[p] + ks * 32);
                ldmx4(bl4[p], kLo + kb_off[p] + ks * 32);
            }
#pragma unroll
            for (int p = 0; p < 4; p++) {
                mma16816(sc[2 * p + 0], qf[0][ks], bh4[p][0], bh4[p][1]);
                mma16816(sc[2 * p + 1], qf[0][ks], bh4[p][2], bh4[p][3]);
            }
#pragma unroll
            for (int p = 0; p < 4; p++) {
                mma16816(sc[2 * p + 0], qf[0][ks], bl4[p][0], bl4[p][1]);
                mma16816(sc[2 * p + 1], qf[0][ks], bl4[p][2], bl4[p][3]);
            }
#pragma unroll
            for (int p = 0; p < 4; p++) {
                mma16816(sc[2 * p + 0], qf[1][ks], bh4[p][0], bh4[p][1]);
                mma16816(sc[2 * p + 1], qf[1][ks], bh4[p][2], bh4[p][3]);
            }
        }

        if (kt == q0 - HALFW || kt == q0 + HALFW) {
#pragma unroll
            for (int ni = 0; ni < 8; ni++)
#pragma unroll
                for (int e = 0; e < 4; e++) {
                    const int kc = kt + ni * 8 + c_lane + (e & 1);
                    const int qa = q0 + wid * 16 + r_lane + ((e >> 1) << 3);
                    const int d = kc - qa;
                    if (d < -HALFW || d > HALFW) sc[ni][e] = -3.0e38f;
                }
        }

        float mx0 = -3.0e38f, mx1 = -3.0e38f;
#pragma unroll
        for (int ni = 0; ni < 8; ni++) {
            mx0 = fmaxf(mx0, fmaxf(sc[ni][0], sc[ni][1]));
            mx1 = fmaxf(mx1, fmaxf(sc[ni][2], sc[ni][3]));
        }
        mx0 = fmaxf(mx0, __shfl_xor_sync(0xffffffffu, mx0, 1));
        mx0 = fmaxf(mx0, __shfl_xor_sync(0xffffffffu, mx0, 2));
        mx1 = fmaxf(mx1, __shfl_xor_sync(0xffffffffu, mx1, 1));
        mx1 = fmaxf(mx1, __shfl_xor_sync(0xffffffffu, mx1, 2));

        const float nm0 = fmaxf(m_r[0], mx0);
        const float nm1 = fmaxf(m_r[1], mx1);
        const float c0 = exp2f(m_r[0] - nm0);
        const float c1 = exp2f(m_r[1] - nm1);
        float s0 = 0.0f, s1 = 0.0f;
#pragma unroll
        for (int ni = 0; ni < 8; ni++) {
            sc[ni][0] = exp2f(sc[ni][0] - nm0); s0 += sc[ni][0];
            sc[ni][1] = exp2f(sc[ni][1] - nm0); s0 += sc[ni][1];
            sc[ni][2] = exp2f(sc[ni][2] - nm1); s1 += sc[ni][2];
            sc[ni][3] = exp2f(sc[ni][3] - nm1); s1 += sc[ni][3];
        }
        s0 += __shfl_xor_sync(0xffffffffu, s0, 1);
        s0 += __shfl_xor_sync(0xffffffffu, s0, 2);
        s1 += __shfl_xor_sync(0xffffffffu, s1, 1);
        s1 += __shfl_xor_sync(0xffffffffu, s1, 2);
        l_r[0] = l_r[0] * c0 + s0; m_r[0] = nm0;
        l_r[1] = l_r[1] * c1 + s1; m_r[1] = nm1;
#pragma unroll
        for (int ni = 0; ni < 8; ni++) {
            o[ni][0] *= c0; o[ni][1] *= c0;
            o[ni][2] *= c1; o[ni][3] *= c1;
        }

#pragma unroll
        for (int ks = 0; ks < 4; ks++) {
            u32 ph[4], pl[4];
            split_pair(sc[2 * ks + 0][0], sc[2 * ks + 0][1], ph[0], pl[0]);
            split_pair(sc[2 * ks + 0][2], sc[2 * ks + 0][3], ph[1], pl[1]);
            split_pair(sc[2 * ks + 1][0], sc[2 * ks + 1][1], ph[2], pl[2]);
            split_pair(sc[2 * ks + 1][2], sc[2 * ks + 1][3], ph[3], pl[3]);
            u32 vh4[4][4], vl4[4][4];
#pragma unroll
            for (int p = 0; p < 4; p++) {
                ldmx4t(vh4[p], vHi + v_off + ks * 16 * AROWB + p * 32);
                ldmx4t(vl4[p], vLo + v_off + ks * 16 * AROWB + p * 32);
            }
#pragma unroll
            for (int p = 0; p < 4; p++) {
                mma16816(o[2 * p + 0], ph, vh4[p][0], vh4[p][1]);
                mma16816(o[2 * p + 1], ph, vh4[p][2], vh4[p][3]);
            }
#pragma unroll
            for (int p = 0; p < 4; p++) {
                mma16816(o[2 * p + 0], ph, vl4[p][0], vl4[p][1]);
                mma16816(o[2 * p + 1], ph, vl4[p][2], vl4[p][3]);
            }
#pragma unroll
            for (int p = 0; p < 4; p++) {
                mma16816(o[2 * p + 0], pl, vh4[p][0], vh4[p][1]);
                mma16816(o[2 * p + 1], pl, vh4[p][2], vh4[p][3]);
            }
        }
        __syncthreads();
    }

    const float inv0 = 1.0f / l_r[0];
    const float inv1 = 1.0f / l_r[1];
    const int s_row0 = q0 + wid * 16 + r_lane;
#pragma unroll
    for (int ni = 0; ni < 8; ni++) {
        const int dcol = ni * 8 + c_lane;
        const size_t base = (size_t)b * EMB + h * HDIM + dcol;
        float2 r0, r1;
        r0.x = o[ni][0] * inv0; r0.y = o[ni][1] * inv0;
        r1.x = o[ni][2] * inv1; r1.y = o[ni][3] * inv1;
        *(float2*)(out + (size_t)s_row0 * (BATCH * EMB) + base) = r0;
        *(float2*)(out + (size_t)(s_row0 + 8) * (BATCH * EMB) + base) = r1;
    }
}

extern "C" void kernel_launch(void* const* d_in, const int* in_sizes, int n_in,
                              void* d_out, int out_size) {
    (void)in_sizes; (void)n_in; (void)out_size;
    const float* X  = (const float*)d_in[0];
    const float* Wq = (const float*)d_in[1];
    const float* bq = (const float*)d_in[2];
    const float* Wk = (const float*)d_in[3];
    const float* bk = (const float*)d_in[4];
    const float* Wv = (const float*)d_in[5];
    const float* bv = (const float*)d_in[6];
    float* out = (float*)d_out;

    static int attr_set = 0;
    if (!attr_set) {
        cudaFuncSetAttribute(gemm_fp16_kernel,
                             cudaFuncAttributeMaxDynamicSharedMemorySize, GEMM_SMEM);
        cudaFuncSetAttribute(attn_mma_kernel,
                             cudaFuncAttributeMaxDynamicSharedMemorySize, AT_SMEM);
        attr_set = 1;
    }

    conv_xw_kernel<<<XBLKS + 1728, 256>>>(X, Wq, Wk, Wv);

    dim3 gg(MROWS / 128, EMB / 64, 3);    // (64, 12, 3)
    gemm_fp16_kernel<<<gg, 256, GEMM_SMEM>>>(bq, bk, bv);

    dim3 ga(SEQ / 64, NHEAD, BATCH);
    attn_mma_kernel<<<ga, 128, AT_SMEM>>>(out);
}